// round 8
// baseline (speedup 1.0000x reference)
#include <cuda_runtime.h>
#include <cstdint>

#define N_NODES 100000
#define N_EDGES 1600000
#define HID 64

#define SCAN_BLK 1024
#define N_SCAN_BLOCKS ((N_NODES + SCAN_BLK - 1) / SCAN_BLK)   // 98

#define N_CHUNKS 4
#define CHUNK_NODES (N_NODES / N_CHUNKS)      // 25000

// ---- device-global scratch (no allocations allowed) ----
// Double-buffered xw: gathers read the whole buffer (random src rows), so the
// next layer's GEMM must write the OTHER buffer (WAR hazard otherwise).
__device__ float g_xw_a[(size_t)N_NODES * HID];
__device__ float g_xw_b[(size_t)N_NODES * HID];
__device__ int   g_deg[N_NODES];
__device__ int   g_off[N_NODES + 1];
__device__ int   g_col[N_EDGES];
__device__ int   g_part[N_SCAN_BLOCKS];
__device__ int   g_idx_is64;

// ---------------------------------------------------------------------------
__global__ __launch_bounds__(256) void zero_deg_detect(const int* __restrict__ ei_raw) {
    int i = blockIdx.x * 256 + threadIdx.x;
    if (i < N_NODES) g_deg[i] = 0;
    if (blockIdx.x == 0 && threadIdx.x == 0) {
        int is64 = 1;
        for (int j = 0; j < 256; j++) {
            int lo = ei_raw[2 * j];
            int hi = ei_raw[2 * j + 1];
            if (hi != 0 || (unsigned)lo >= (unsigned)N_NODES) { is64 = 0; break; }
        }
        g_idx_is64 = is64;
    }
}

__device__ __forceinline__ int load_idx(const int* __restrict__ ei, size_t pos) {
    return g_idx_is64 ? __ldg(&ei[2 * pos]) : __ldg(&ei[pos]);
}

__global__ __launch_bounds__(256) void count_deg(const int* __restrict__ ei) {
    int e = blockIdx.x * 256 + threadIdx.x;
    if (e < N_EDGES) {
        int dst = load_idx(ei, (size_t)N_EDGES + e);
        atomicAdd(&g_deg[dst], 1);
    }
}

__global__ __launch_bounds__(SCAN_BLK) void scan_blocks() {
    __shared__ int warpsums[32];
    const int tid = threadIdx.x, lane = tid & 31, wid = tid >> 5;
    const int i = blockIdx.x * SCAN_BLK + tid;

    int v = (i < N_NODES) ? g_deg[i] : 0;
    int s = v;
    #pragma unroll
    for (int d = 1; d < 32; d <<= 1) {
        int t = __shfl_up_sync(0xffffffffu, s, d);
        if (lane >= d) s += t;
    }
    if (lane == 31) warpsums[wid] = s;
    __syncthreads();
    if (wid == 0) {
        int ws = warpsums[lane];
        #pragma unroll
        for (int d = 1; d < 32; d <<= 1) {
            int t = __shfl_up_sync(0xffffffffu, ws, d);
            if (lane >= d) ws += t;
        }
        warpsums[lane] = ws;
    }
    __syncthreads();
    int warpoff = (wid == 0) ? 0 : warpsums[wid - 1];
    if (i < N_NODES) g_off[i] = warpoff + s - v;
    if (tid == SCAN_BLK - 1) g_part[blockIdx.x] = warpsums[31];
}

__global__ __launch_bounds__(SCAN_BLK) void scan_finish() {
    __shared__ int soff;
    const int tid = threadIdx.x;
    if (tid < 32) {
        int sum = 0;
        for (int j = tid; j < blockIdx.x; j += 32) sum += g_part[j];
        #pragma unroll
        for (int d = 16; d > 0; d >>= 1)
            sum += __shfl_xor_sync(0xffffffffu, sum, d);
        if (tid == 0) soff = sum;
    }
    __syncthreads();
    int off = soff;
    int i = blockIdx.x * SCAN_BLK + tid;
    if (i < N_NODES) {
        g_off[i] += off;
        g_deg[i] = 0;
    }
    if (blockIdx.x == N_SCAN_BLOCKS - 1 && tid == 0)
        g_off[N_NODES] = off + g_part[N_SCAN_BLOCKS - 1];
}

__global__ __launch_bounds__(256) void fill_csr(const int* __restrict__ ei) {
    int e = blockIdx.x * 256 + threadIdx.x;
    if (e < N_EDGES) {
        int src = load_idx(ei, (size_t)e);
        int dst = load_idx(ei, (size_t)N_EDGES + e);
        int slot = g_off[dst] + atomicAdd(&g_deg[dst], 1);
        g_col[slot] = src;
    }
}

// ---------------------------------------------------------------------------
// GEMM over row range [row_base, row_end): Y[n,:] = X[n,:] @ W
// ---------------------------------------------------------------------------
template <int K>
__global__ __launch_bounds__(128) void gemm_f(const float* __restrict__ X,
                                              const float* __restrict__ W,
                                              float* __restrict__ Y,
                                              int row_base, int row_end) {
    __shared__ float sW[32][64];
    __shared__ float sXt[32][136];

    const int tid  = threadIdx.x;
    const int colg = tid & 7;
    const int rowg = tid >> 3;
    const int row0 = row_base + blockIdx.x * 128;

    float acc[8][8] = {};

    for (int kc = 0; kc < K; kc += 32) {
        __syncthreads();
        #pragma unroll
        for (int j = 0; j < 4; j++) {
            int i4 = (j * 128 + tid) * 4;
            int r = i4 >> 6, c = i4 & 63;
            *(float4*)&sW[r][c] = *(const float4*)&W[(size_t)(kc + r) * 64 + c];
        }
        #pragma unroll
        for (int j = 0; j < 8; j++) {
            int r  = j * 16 + (tid >> 3);
            int k4 = (tid & 7) * 4;
            int grow = row0 + r;
            float4 v = (grow < row_end)
                     ? *(const float4*)&X[(size_t)grow * K + kc + k4]
                     : make_float4(0.f, 0.f, 0.f, 0.f);
            sXt[k4 + 0][r] = v.x;
            sXt[k4 + 1][r] = v.y;
            sXt[k4 + 2][r] = v.z;
            sXt[k4 + 3][r] = v.w;
        }
        __syncthreads();

        #pragma unroll
        for (int k = 0; k < 32; k++) {
            float xv[8], wv[8];
            *(float4*)&xv[0] = *(float4*)&sXt[k][rowg * 8];
            *(float4*)&xv[4] = *(float4*)&sXt[k][rowg * 8 + 4];
            *(float4*)&wv[0] = *(float4*)&sW[k][colg * 8];
            *(float4*)&wv[4] = *(float4*)&sW[k][colg * 8 + 4];
            #pragma unroll
            for (int r = 0; r < 8; r++)
                #pragma unroll
                for (int c = 0; c < 8; c++)
                    acc[r][c] = fmaf(xv[r], wv[c], acc[r][c]);
        }
    }

    #pragma unroll
    for (int r = 0; r < 8; r++) {
        int grow = row0 + rowg * 8 + r;
        if (grow < row_end) {
            *(float4*)&Y[(size_t)grow * 64 + colg * 8]     = *(float4*)&acc[r][0];
            *(float4*)&Y[(size_t)grow * 64 + colg * 8 + 4] = *(float4*)&acc[r][4];
        }
    }
}

// ---------------------------------------------------------------------------
// CSR gather over node range [node_base, node_base+node_cnt)
// ---------------------------------------------------------------------------
__global__ __launch_bounds__(256) void gather64(const float* __restrict__ xw,
                                                float* __restrict__ out,
                                                const float* __restrict__ b,
                                                int node_base, int node_cnt) {
    int w = (blockIdx.x * 256 + threadIdx.x) >> 5;
    if (w >= node_cnt) return;
    int node = node_base + w;
    const int lane = threadIdx.x & 31;
    const int half = lane >> 4;
    const int q    = lane & 15;

    const int beg = __ldg(&g_off[node]);
    const int end = __ldg(&g_off[node + 1]);

    float4 acc = make_float4(0.f, 0.f, 0.f, 0.f);
    int i = beg + half;
    int nxt = (i < end) ? __ldg(&g_col[i]) : 0;
    while (i < end) {
        int src = nxt;
        int j = i + 2;
        if (j < end) nxt = __ldg(&g_col[j]);
        float4 v = *reinterpret_cast<const float4*>(xw + (size_t)src * 64 + q * 4);
        acc.x += v.x; acc.y += v.y; acc.z += v.z; acc.w += v.w;
        i = j;
    }
    acc.x += __shfl_xor_sync(0xffffffffu, acc.x, 16);
    acc.y += __shfl_xor_sync(0xffffffffu, acc.y, 16);
    acc.z += __shfl_xor_sync(0xffffffffu, acc.z, 16);
    acc.w += __shfl_xor_sync(0xffffffffu, acc.w, 16);

    if (half == 0) {
        float4 bv = reinterpret_cast<const float4*>(b)[q];
        acc.x += bv.x; acc.y += bv.y; acc.z += bv.z; acc.w += bv.w;
        *reinterpret_cast<float4*>(out + (size_t)node * 64 + q * 4) = acc;
    }
}

// ---------------------------------------------------------------------------
extern "C" void kernel_launch(void* const* d_in, const int* in_sizes, int n_in,
                              void* d_out, int out_size) {
    const float* x  = (const float*)d_in[0];
    const int*   ei = (const int*)d_in[1];
    const float* W1 = (const float*)d_in[2];
    const float* b1 = (const float*)d_in[3];
    const float* W2 = (const float*)d_in[4];
    const float* b2 = (const float*)d_in[5];
    const float* W3 = (const float*)d_in[6];
    const float* b3 = (const float*)d_in[7];

    float* h1 = (float*)d_out;
    float* h2 = h1 + (size_t)N_NODES * HID;
    float* h3 = h2 + (size_t)N_NODES * HID;

    float *xw_a, *xw_b;
    cudaGetSymbolAddress((void**)&xw_a, g_xw_a);
    cudaGetSymbolAddress((void**)&xw_b, g_xw_b);

    const int ggrid_full  = (N_NODES + 127) / 128;
    const int ggrid_chunk = (CHUNK_NODES + 127) / 128;
    const int egrid = (N_EDGES + 255) / 256;
    const int ngrid = (N_NODES + 255) / 256;
    const int agrid_chunk = (CHUNK_NODES * 32 + 255) / 256;
    const int agrid_full  = (N_NODES * 32 + 255) / 256;

    // Host-side resources created once (no device memory involved).
    static cudaStream_t sB = nullptr;
    static cudaEvent_t  ev_fork = nullptr, ev_csr = nullptr;
    static cudaEvent_t  ev_g1[N_CHUNKS], ev_g2[N_CHUNKS];
    static cudaEvent_t  ev_w2 = nullptr, ev_w3 = nullptr;
    if (sB == nullptr) {
        cudaStreamCreateWithFlags(&sB, cudaStreamNonBlocking);
        cudaEventCreateWithFlags(&ev_fork, cudaEventDisableTiming);
        cudaEventCreateWithFlags(&ev_csr,  cudaEventDisableTiming);
        cudaEventCreateWithFlags(&ev_w2,   cudaEventDisableTiming);
        cudaEventCreateWithFlags(&ev_w3,   cudaEventDisableTiming);
        for (int c = 0; c < N_CHUNKS; c++) {
            cudaEventCreateWithFlags(&ev_g1[c], cudaEventDisableTiming);
            cudaEventCreateWithFlags(&ev_g2[c], cudaEventDisableTiming);
        }
    }

    // --- Fork: CSR build on stream B, GEMM1 on main stream ---
    cudaEventRecord(ev_fork, 0);
    cudaStreamWaitEvent(sB, ev_fork, 0);

    zero_deg_detect<<<ngrid, 256, 0, sB>>>(ei);
    count_deg<<<egrid, 256, 0, sB>>>(ei);
    scan_blocks<<<N_SCAN_BLOCKS, SCAN_BLK, 0, sB>>>();
    scan_finish<<<N_SCAN_BLOCKS, SCAN_BLK, 0, sB>>>();
    fill_csr<<<egrid, 256, 0, sB>>>(ei);
    cudaEventRecord(ev_csr, sB);

    gemm_f<128><<<ggrid_full, 128>>>(x, W1, xw_a, 0, N_NODES);   // main stream

    cudaStreamWaitEvent(0, ev_csr, 0);     // gather1 needs CSR + xw_a

    // --- gather1 (reads xw_a) chunks on main; gemm2 (writes xw_b) on B ---
    for (int c = 0; c < N_CHUNKS; c++) {
        int base = c * CHUNK_NODES;
        gather64<<<agrid_chunk, 256>>>(xw_a, h1, b1, base, CHUNK_NODES);
        cudaEventRecord(ev_g1[c], 0);
        cudaStreamWaitEvent(sB, ev_g1[c], 0);
        gemm_f<64><<<ggrid_chunk, 128, 0, sB>>>(h1, W2, xw_b, base, base + CHUNK_NODES);
    }
    cudaEventRecord(ev_w2, sB);
    cudaStreamWaitEvent(0, ev_w2, 0);      // gather2 needs all of xw_b

    // --- gather2 (reads xw_b) chunks on main; gemm3 (writes xw_a) on B ---
    // xw_a is safe to overwrite: all its readers (gather1 chunks) precede
    // ev_w2 on the main stream, and gemm3 chunk c waits on gather2 chunk c.
    for (int c = 0; c < N_CHUNKS; c++) {
        int base = c * CHUNK_NODES;
        gather64<<<agrid_chunk, 256>>>(xw_b, h2, b2, base, CHUNK_NODES);
        cudaEventRecord(ev_g2[c], 0);
        cudaStreamWaitEvent(sB, ev_g2[c], 0);
        gemm_f<64><<<ggrid_chunk, 128, 0, sB>>>(h2, W3, xw_a, base, base + CHUNK_NODES);
    }
    cudaEventRecord(ev_w3, sB);
    cudaStreamWaitEvent(0, ev_w3, 0);      // gather3 needs all of xw_a

    gather64<<<agrid_full, 256>>>(xw_a, h3, b3, 0, N_NODES);
}

// round 9
// speedup vs baseline: 1.2485x; 1.2485x over previous
#include <cuda_runtime.h>
#include <cuda_fp16.h>
#include <cstdint>

#define N_NODES 100000
#define N_EDGES 1600000
#define HID 64

#define SCAN_BLK 1024
#define N_SCAN_BLOCKS ((N_NODES + SCAN_BLK - 1) / SCAN_BLK)   // 98

// ---- device-global scratch (no allocations allowed) ----
// xw stored in fp16: halves the L2 read traffic of the (bandwidth-bound)
// gathers. Accumulation is fp32; outputs h1..h3 are fp32.
__device__ __half g_xwh[(size_t)N_NODES * HID];
__device__ int    g_deg[N_NODES];
__device__ int    g_off[N_NODES + 1];
__device__ int    g_col[N_EDGES];
__device__ int    g_part[N_SCAN_BLOCKS];
__device__ int    g_idx_is64;

// ---------------------------------------------------------------------------
__global__ __launch_bounds__(256) void zero_deg_detect(const int* __restrict__ ei_raw) {
    int i = blockIdx.x * 256 + threadIdx.x;
    if (i < N_NODES) g_deg[i] = 0;
    if (blockIdx.x == 0 && threadIdx.x == 0) {
        int is64 = 1;
        for (int j = 0; j < 256; j++) {
            int lo = ei_raw[2 * j];
            int hi = ei_raw[2 * j + 1];
            if (hi != 0 || (unsigned)lo >= (unsigned)N_NODES) { is64 = 0; break; }
        }
        g_idx_is64 = is64;
    }
}

__device__ __forceinline__ int load_idx(const int* __restrict__ ei, size_t pos) {
    return g_idx_is64 ? __ldg(&ei[2 * pos]) : __ldg(&ei[pos]);
}

__global__ __launch_bounds__(256) void count_deg(const int* __restrict__ ei) {
    int e = blockIdx.x * 256 + threadIdx.x;
    if (e < N_EDGES) {
        int dst = load_idx(ei, (size_t)N_EDGES + e);
        atomicAdd(&g_deg[dst], 1);
    }
}

__global__ __launch_bounds__(SCAN_BLK) void scan_blocks() {
    __shared__ int warpsums[32];
    const int tid = threadIdx.x, lane = tid & 31, wid = tid >> 5;
    const int i = blockIdx.x * SCAN_BLK + tid;

    int v = (i < N_NODES) ? g_deg[i] : 0;
    int s = v;
    #pragma unroll
    for (int d = 1; d < 32; d <<= 1) {
        int t = __shfl_up_sync(0xffffffffu, s, d);
        if (lane >= d) s += t;
    }
    if (lane == 31) warpsums[wid] = s;
    __syncthreads();
    if (wid == 0) {
        int ws = warpsums[lane];
        #pragma unroll
        for (int d = 1; d < 32; d <<= 1) {
            int t = __shfl_up_sync(0xffffffffu, ws, d);
            if (lane >= d) ws += t;
        }
        warpsums[lane] = ws;
    }
    __syncthreads();
    int warpoff = (wid == 0) ? 0 : warpsums[wid - 1];
    if (i < N_NODES) g_off[i] = warpoff + s - v;
    if (tid == SCAN_BLK - 1) g_part[blockIdx.x] = warpsums[31];
}

__global__ __launch_bounds__(SCAN_BLK) void scan_finish() {
    __shared__ int soff;
    const int tid = threadIdx.x;
    if (tid < 32) {
        int sum = 0;
        for (int j = tid; j < blockIdx.x; j += 32) sum += g_part[j];
        #pragma unroll
        for (int d = 16; d > 0; d >>= 1)
            sum += __shfl_xor_sync(0xffffffffu, sum, d);
        if (tid == 0) soff = sum;
    }
    __syncthreads();
    int off = soff;
    int i = blockIdx.x * SCAN_BLK + tid;
    if (i < N_NODES) {
        g_off[i] += off;
        g_deg[i] = 0;
    }
    if (blockIdx.x == N_SCAN_BLOCKS - 1 && tid == 0)
        g_off[N_NODES] = off + g_part[N_SCAN_BLOCKS - 1];
}

__global__ __launch_bounds__(256) void fill_csr(const int* __restrict__ ei) {
    int e = blockIdx.x * 256 + threadIdx.x;
    if (e < N_EDGES) {
        int src = load_idx(ei, (size_t)e);
        int dst = load_idx(ei, (size_t)N_EDGES + e);
        int slot = g_off[dst] + atomicAdd(&g_deg[dst], 1);
        g_col[slot] = src;
    }
}

// ---------------------------------------------------------------------------
// GEMM: Y[n, 0..63] = X[n, 0..K-1] @ W[K, 64], Y stored as fp16.
// 128x64 tile, 128 threads, 8x8/thread, k-chunk 32, transposed X staging.
// ---------------------------------------------------------------------------
template <int K>
__global__ __launch_bounds__(128) void gemm_f(const float* __restrict__ X,
                                              const float* __restrict__ W,
                                              __half* __restrict__ Y,
                                              int nrows) {
    __shared__ float sW[32][64];
    __shared__ float sXt[32][136];

    const int tid  = threadIdx.x;
    const int colg = tid & 7;
    const int rowg = tid >> 3;
    const int row0 = blockIdx.x * 128;

    float acc[8][8] = {};

    for (int kc = 0; kc < K; kc += 32) {
        __syncthreads();
        #pragma unroll
        for (int j = 0; j < 4; j++) {
            int i4 = (j * 128 + tid) * 4;
            int r = i4 >> 6, c = i4 & 63;
            *(float4*)&sW[r][c] = *(const float4*)&W[(size_t)(kc + r) * 64 + c];
        }
        #pragma unroll
        for (int j = 0; j < 8; j++) {
            int r  = j * 16 + (tid >> 3);
            int k4 = (tid & 7) * 4;
            int grow = row0 + r;
            float4 v = (grow < nrows)
                     ? *(const float4*)&X[(size_t)grow * K + kc + k4]
                     : make_float4(0.f, 0.f, 0.f, 0.f);
            sXt[k4 + 0][r] = v.x;
            sXt[k4 + 1][r] = v.y;
            sXt[k4 + 2][r] = v.z;
            sXt[k4 + 3][r] = v.w;
        }
        __syncthreads();

        #pragma unroll
        for (int k = 0; k < 32; k++) {
            float xv[8], wv[8];
            *(float4*)&xv[0] = *(float4*)&sXt[k][rowg * 8];
            *(float4*)&xv[4] = *(float4*)&sXt[k][rowg * 8 + 4];
            *(float4*)&wv[0] = *(float4*)&sW[k][colg * 8];
            *(float4*)&wv[4] = *(float4*)&sW[k][colg * 8 + 4];
            #pragma unroll
            for (int r = 0; r < 8; r++)
                #pragma unroll
                for (int c = 0; c < 8; c++)
                    acc[r][c] = fmaf(xv[r], wv[c], acc[r][c]);
        }
    }

    #pragma unroll
    for (int r = 0; r < 8; r++) {
        int grow = row0 + rowg * 8 + r;
        if (grow < nrows) {
            __half2 p0 = __floats2half2_rn(acc[r][0], acc[r][1]);
            __half2 p1 = __floats2half2_rn(acc[r][2], acc[r][3]);
            __half2 p2 = __floats2half2_rn(acc[r][4], acc[r][5]);
            __half2 p3 = __floats2half2_rn(acc[r][6], acc[r][7]);
            uint4 pack;
            pack.x = *reinterpret_cast<uint32_t*>(&p0);
            pack.y = *reinterpret_cast<uint32_t*>(&p1);
            pack.z = *reinterpret_cast<uint32_t*>(&p2);
            pack.w = *reinterpret_cast<uint32_t*>(&p3);
            // byte offset = grow*128 + colg*16 -> 16B aligned
            *reinterpret_cast<uint4*>(Y + (size_t)grow * 64 + colg * 8) = pack;
        }
    }
}

// ---------------------------------------------------------------------------
// CSR gather-aggregate (fp16 source rows, fp32 accumulate):
//   out[n,:] = sum_{e in in(n)} xw[col[e],:] + b
// One warp per node; half-warps alternate edges; lane owns 4 features (8 B).
// ---------------------------------------------------------------------------
__global__ __launch_bounds__(256) void gather64(const __half* __restrict__ xw,
                                                float* __restrict__ out,
                                                const float* __restrict__ b) {
    int node = (blockIdx.x * 256 + threadIdx.x) >> 5;
    if (node >= N_NODES) return;
    const int lane = threadIdx.x & 31;
    const int half = lane >> 4;
    const int q    = lane & 15;

    const int beg = __ldg(&g_off[node]);
    const int end = __ldg(&g_off[node + 1]);

    float4 acc = make_float4(0.f, 0.f, 0.f, 0.f);
    int i = beg + half;
    int nxt = (i < end) ? __ldg(&g_col[i]) : 0;
    while (i < end) {
        int src = nxt;
        int j = i + 2;
        if (j < end) nxt = __ldg(&g_col[j]);
        uint2 raw = *reinterpret_cast<const uint2*>(xw + (size_t)src * 64 + q * 4);
        __half2 h0 = *reinterpret_cast<__half2*>(&raw.x);
        __half2 h1 = *reinterpret_cast<__half2*>(&raw.y);
        float2 f0 = __half22float2(h0);
        float2 f1 = __half22float2(h1);
        acc.x += f0.x; acc.y += f0.y; acc.z += f1.x; acc.w += f1.y;
        i = j;
    }
    acc.x += __shfl_xor_sync(0xffffffffu, acc.x, 16);
    acc.y += __shfl_xor_sync(0xffffffffu, acc.y, 16);
    acc.z += __shfl_xor_sync(0xffffffffu, acc.z, 16);
    acc.w += __shfl_xor_sync(0xffffffffu, acc.w, 16);

    if (half == 0) {
        float4 bv = reinterpret_cast<const float4*>(b)[q];
        acc.x += bv.x; acc.y += bv.y; acc.z += bv.z; acc.w += bv.w;
        *reinterpret_cast<float4*>(out + (size_t)node * 64 + q * 4) = acc;
    }
}

// ---------------------------------------------------------------------------
extern "C" void kernel_launch(void* const* d_in, const int* in_sizes, int n_in,
                              void* d_out, int out_size) {
    const float* x  = (const float*)d_in[0];
    const int*   ei = (const int*)d_in[1];
    const float* W1 = (const float*)d_in[2];
    const float* b1 = (const float*)d_in[3];
    const float* W2 = (const float*)d_in[4];
    const float* b2 = (const float*)d_in[5];
    const float* W3 = (const float*)d_in[6];
    const float* b3 = (const float*)d_in[7];

    float* h1 = (float*)d_out;
    float* h2 = h1 + (size_t)N_NODES * HID;
    float* h3 = h2 + (size_t)N_NODES * HID;

    __half* xw;
    cudaGetSymbolAddress((void**)&xw, g_xwh);

    const int ggrid = (N_NODES + 127) / 128;
    const int egrid = (N_EDGES + 255) / 256;
    const int ngrid = (N_NODES + 255) / 256;
    const int agrid = (N_NODES * 32 + 255) / 256;

    // Host-side resources created once (no device memory involved).
    static cudaStream_t sB = nullptr;
    static cudaEvent_t  ev_fork = nullptr, ev_csr = nullptr;
    if (sB == nullptr) {
        cudaStreamCreateWithFlags(&sB, cudaStreamNonBlocking);
        cudaEventCreateWithFlags(&ev_fork, cudaEventDisableTiming);
        cudaEventCreateWithFlags(&ev_csr,  cudaEventDisableTiming);
    }

    // --- Fork: CSR build on stream B, GEMM1 (compute-bound) on main stream ---
    cudaEventRecord(ev_fork, 0);
    cudaStreamWaitEvent(sB, ev_fork, 0);

    zero_deg_detect<<<ngrid, 256, 0, sB>>>(ei);
    count_deg<<<egrid, 256, 0, sB>>>(ei);
    scan_blocks<<<N_SCAN_BLOCKS, SCAN_BLK, 0, sB>>>();
    scan_finish<<<N_SCAN_BLOCKS, SCAN_BLK, 0, sB>>>();
    fill_csr<<<egrid, 256, 0, sB>>>(ei);
    cudaEventRecord(ev_csr, sB);

    gemm_f<128><<<ggrid, 128>>>(x, W1, xw, N_NODES);   // main stream

    cudaStreamWaitEvent(0, ev_csr, 0);     // gather1 needs CSR + xw

    // --- serial layers (R6 topology; concurrency beyond this regressed) ---
    gather64<<<agrid, 256>>>(xw, h1, b1);
    gemm_f<64><<<ggrid, 128>>>(h1, W2, xw, N_NODES);
    gather64<<<agrid, 256>>>(xw, h2, b2);
    gemm_f<64><<<ggrid, 128>>>(h2, W3, xw, N_NODES);
    gather64<<<agrid, 256>>>(xw, h3, b3);
}